// round 1
// baseline (speedup 1.0000x reference)
#include <cuda_runtime.h>
#include <cuda_bf16.h>
#include <stdint.h>

// Flag: 1 if T is stored as int64, 0 if int32. Written by detect_kernel,
// read by gather_kernel. Deterministic for fixed inputs.
__device__ int g_t_is_int64;

// Detect index dtype by inspecting the first 32 odd 32-bit words of T.
// If T is int64 (little-endian, values < 366), every odd word is the zero
// high-half. If T is int32, odd words are random indices into dims of size
// 24/60/366/7 — all 32 being zero has probability ~1e-50.
__global__ void detect_dtype_kernel(const unsigned int* __restrict__ t32) {
    if (threadIdx.x == 0 && blockIdx.x == 0) {
        int is64 = 1;
        #pragma unroll
        for (int k = 0; k < 32; k++) {
            if (t32[2 * k + 1] != 0u) is64 = 0;
        }
        g_t_is_int64 = is64;
    }
}

// Warp-per-row gather. Lane j: table = j>>3, sub-float4 = j&7.
// Row output = [W0[t0] | W1[t1] | W2[t2] | W3[t3]] (4 x 32 floats = 128).
__global__ void __launch_bounds__(256)
time_encoder_gather_kernel(const void* __restrict__ Tv,
                           const float4* __restrict__ W0,
                           const float4* __restrict__ W1,
                           const float4* __restrict__ W2,
                           const float4* __restrict__ W3,
                           float4* __restrict__ out,
                           int N) {
    const int lane = threadIdx.x & 31;
    const int dim  = lane >> 3;   // which table (0..3)
    const int sub  = lane & 7;    // which float4 within the 32-float slice

    // Per-lane table base pointer (loop-invariant).
    const float4* W = (dim == 0) ? W0 : (dim == 1) ? W1 : (dim == 2) ? W2 : W3;

    const int warp   = (int)((blockIdx.x * blockDim.x + threadIdx.x) >> 5);
    const int nwarps = (int)((gridDim.x * blockDim.x) >> 5);

    const bool is64 = (g_t_is_int64 != 0);
    const int*       T32 = (const int*)Tv;
    const long long* T64 = (const long long*)Tv;

    for (int row = warp; row < N; row += nwarps) {
        int idx;
        if (is64) {
            idx = (int)__ldg(&T64[row * 4 + dim]);
        } else {
            idx = __ldg(&T32[row * 4 + dim]);
        }
        // Tables are tiny (57KB total) -> L1-resident gather.
        float4 v = __ldg(&W[idx * 8 + sub]);
        // Output is write-once streaming data: evict-first store.
        __stcs(&out[(size_t)row * 32 + lane], v);
    }
}

extern "C" void kernel_launch(void* const* d_in, const int* in_sizes, int n_in,
                              void* d_out, int out_size) {
    const void*   T  = d_in[0];
    const float4* W0 = (const float4*)d_in[1];
    const float4* W1 = (const float4*)d_in[2];
    const float4* W2 = (const float4*)d_in[3];
    const float4* W3 = (const float4*)d_in[4];
    float4* out = (float4*)d_out;

    const int N = in_sizes[0] / 4;  // T has N*4 index elements

    detect_dtype_kernel<<<1, 32>>>((const unsigned int*)T);

    // Grid-stride: ~28K warps, ~70 rows each. 148 SMs x 24 blocks.
    const int threads = 256;
    const int blocks  = 148 * 24;
    time_encoder_gather_kernel<<<blocks, threads>>>(T, W0, W1, W2, W3, out, N);
}

// round 2
// speedup vs baseline: 1.0166x; 1.0166x over previous
#include <cuda_runtime.h>
#include <cuda_bf16.h>
#include <stdint.h>

// Warp-per-2-rows gather. Lane j: table = j>>3, sub-float4 = j&7.
// Row output = [W0[t0] | W1[t1] | W2[t2] | W3[t3]] (4 x 32 floats = 128).
//
// Index dtype (int64 vs int32) is detected in-kernel: each warp inspects the
// high 32-bit halves of the first 32 words of T. If T is int64 little-endian
// with values < 366, all high halves are zero; if int32, the odd words are
// random indices (dims 366/24/7/60) and P(all 32 zero) ~ 1e-50. One cached
// load + one ballot per warp — removes the separate detection kernel launch.
__global__ void __launch_bounds__(256)
time_encoder_gather_kernel(const void* __restrict__ Tv,
                           const float4* __restrict__ W0,
                           const float4* __restrict__ W1,
                           const float4* __restrict__ W2,
                           const float4* __restrict__ W3,
                           float4* __restrict__ out,
                           int N) {
    const int lane = threadIdx.x & 31;
    const int dim  = lane >> 3;   // which table (0..3)
    const int sub  = lane & 7;    // which float4 within the 32-float slice

    // --- in-warp dtype detection ---
    const unsigned int* t32 = (const unsigned int*)Tv;
    unsigned int hi = __ldg(&t32[2 * lane + 1]);
    const bool is64 = (__ballot_sync(0xFFFFFFFFu, hi != 0u) == 0u);

    // Per-lane table base pointer (loop-invariant).
    const float4* W = (dim == 0) ? W0 : (dim == 1) ? W1 : (dim == 2) ? W2 : W3;

    const int warp   = (int)((blockIdx.x * blockDim.x + threadIdx.x) >> 5);
    const int nwarps = (int)((gridDim.x * blockDim.x) >> 5);

    const int*       T32 = (const int*)Tv;
    const long long* T64 = (const long long*)Tv;

    // Two consecutive rows per iteration: 1KB contiguous store per warp,
    // both gathers in flight before either store issues.
    for (int row = 2 * warp; row < N; row += 2 * nwarps) {
        const int row1 = row + 1;
        const bool has1 = (row1 < N);

        int idx0, idx1 = 0;
        if (is64) {
            idx0 = (int)__ldg(&T64[(size_t)row * 4 + dim]);
            if (has1) idx1 = (int)__ldg(&T64[(size_t)row1 * 4 + dim]);
        } else {
            idx0 = __ldg(&T32[(size_t)row * 4 + dim]);
            if (has1) idx1 = __ldg(&T32[(size_t)row1 * 4 + dim]);
        }

        // Tables total ~57KB -> L1-resident gathers.
        float4 v0 = __ldg(&W[idx0 * 8 + sub]);
        float4 v1;
        if (has1) v1 = __ldg(&W[idx1 * 8 + sub]);

        // Output is write-once streaming data: evict-first stores.
        __stcs(&out[(size_t)row * 32 + lane], v0);
        if (has1) __stcs(&out[(size_t)row1 * 32 + lane], v1);
    }
}

extern "C" void kernel_launch(void* const* d_in, const int* in_sizes, int n_in,
                              void* d_out, int out_size) {
    const void*   T  = d_in[0];
    const float4* W0 = (const float4*)d_in[1];
    const float4* W1 = (const float4*)d_in[2];
    const float4* W2 = (const float4*)d_in[3];
    const float4* W3 = (const float4*)d_in[4];
    float4* out = (float4*)d_out;

    const int N = in_sizes[0] / 4;  // T has N*4 index elements

    const int threads = 256;
    const int blocks  = 148 * 24;
    time_encoder_gather_kernel<<<blocks, threads>>>(T, W0, W1, W2, W3, out, N);
}